// round 4
// baseline (speedup 1.0000x reference)
#include <cuda_runtime.h>
#include <math.h>

// VectorQuantizer: N=65536 (64x32x32 BHWC-flat), C=64, K=1024.
// Output (float32): [quantized 4194304][vq_loss 1][indices 65536][perplexity 1]
// Numerics verified bit-exact in R1:
//   dot: sequential-c fp32 FMA; a=||x||^2 sequential rn(mul)+rn(add);
//   d = rn(rn(a - rn(2*dot)) + esq); argmin first-index ties; out = rn(x + rn(q-x)).

#define NPTS   65536
#define KC     1024
#define CD     64
#define HW     1024
#define MT     128
#define KCH    64
#define NCHUNK (KC / KCH)

#define XP_ 132              // xs pitch: [c][p], natural point pairs
#define EP_ 132              // es pitch: [c][2k], e duplicated (per 64-code chunk)
#define TP_ 68               // x^T pitch for fused quant tail

#define SM_XS  0
#define SM_ES  (CD * XP_)            // 8448 floats
#define SM_AS  (SM_ES + 8704)        // es region: max(64*132=8448, 128*68=8704)
#define SM_IDX (SM_AS + 128)
#define SMEM_FLOATS (SM_IDX + 128)
#define SMEM_BYTES  (SMEM_FLOATS * 4)   // 69,632 B -> 2 blocks/SM

#define OFF_LOSS  4194304
#define OFF_IDX   4194305
#define OFF_PERP  4259841

typedef unsigned long long u64;

__device__ float        g_esq[KC];
__device__ unsigned int g_hist[KC];
__device__ double       g_loss;

__device__ __forceinline__ void unpack2(u64 v, float &lo, float &hi) {
    asm("mov.b64 {%0, %1}, %2;" : "=f"(lo), "=f"(hi) : "l"(v));
}
// packed fp32x2 FMA: each lane is IEEE-rn fp32 FMA (bit-identical to scalar FFMA)
__device__ __forceinline__ void ffma2(u64 &acc, u64 a, u64 b) {
    asm("fma.rn.f32x2 %0, %1, %2, %0;" : "+l"(acc) : "l"(a), "l"(b));
}

__global__ void vq_init() {
    int t = blockIdx.x * blockDim.x + threadIdx.x;
    if (t < KC) g_hist[t] = 0u;
    if (t == 0) g_loss = 0.0;
}

__global__ void vq_esq(const float* __restrict__ emb) {
    int k = blockIdx.x * blockDim.x + threadIdx.x;
    if (k < KC) {
        float s = 0.0f;
        const float* er = emb + (size_t)k * CD;
        #pragma unroll
        for (int c = 0; c < CD; ++c) {
            float e = er[c];
            s = __fadd_rn(s, __fmul_rn(e, e));
        }
        g_esq[k] = s;
    }
}

// ---------------- fused: distances + argmin + quantize + loss + hist ----------------
__global__ void __launch_bounds__(256, 2) vq_main(const float* __restrict__ inputs,
                                                  const float* __restrict__ emb,
                                                  float* __restrict__ out) {
    extern __shared__ float sm[];
    float* xs   = sm + SM_XS;    // [CD][XP_]  x natural (point pairs contiguous)
    float* es   = sm + SM_ES;    // [CD][EP_]  e dup'd per chunk; later x^T [p][TP_]
    float* as_  = sm + SM_AS;    // [128] ||x||^2
    int*   idxs = (int*)(sm + SM_IDX);

    const int t  = threadIdx.x;
    const int tr = t >> 4;       // 16 groups x 8 points
    const int tc = t & 15;       // 16 lanes x 4 codes
    const int n0 = blockIdx.x * MT;
    const int b  = n0 >> 10;
    const int p0 = n0 & 1023;
    const float* xbase = inputs + (size_t)b * (CD * HW) + p0;

    // ---- load x tile [c][p] (coalesced)
    #pragma unroll
    for (int j = 0; j < 8; ++j) {
        int q = t + j * 256;
        int c = q >> 5;
        int g = q & 31;
        float4 v = *reinterpret_cast<const float4*>(xbase + (size_t)c * HW + 4 * g);
        *reinterpret_cast<float4*>(&xs[c * XP_ + 4 * g]) = v;
    }
    __syncthreads();

    // ---- a = ||x||^2 strictly sequential fp32
    if (t < MT) {
        float s = 0.0f;
        #pragma unroll
        for (int c = 0; c < CD; ++c) {
            float xv = xs[c * XP_ + t];
            s = __fadd_rn(s, __fmul_rn(xv, xv));
        }
        as_[t] = s;
    }
    __syncthreads();

    // hoisted point norms (constant over all chunks)
    float a_[8];
    #pragma unroll
    for (int i = 0; i < 8; ++i) a_[i] = as_[tr * 8 + i];

    float bestv[8];
    int   besti[8];
    #pragma unroll
    for (int i = 0; i < 8; ++i) { bestv[i] = __int_as_float(0x7f800000); besti[i] = 0x7fffffff; }

    const float* xr = xs + 8 * tr;
    const float* er = es + 8 * tc;

    #pragma unroll 1
    for (int kc = 0; kc < NCHUNK; ++kc) {
        __syncthreads();   // previous chunk's es readers done
        // ---- stage e chunk, duplicated: es[c][2k] = es[c][2k+1] = e[kc*64+k][c]
        // 1024 float4s; fid = t + 256j -> code k=fid>>4, cgroup cg=fid&15
        #pragma unroll
        for (int j = 0; j < 4; ++j) {
            int fid = t + 256 * j;
            int k   = fid >> 4;
            int cb  = (fid & 15) * 4;
            float4 v = __ldg(reinterpret_cast<const float4*>(
                emb + (size_t)(kc * KCH + k) * CD + cb));
            *reinterpret_cast<float2*>(&es[(cb + 0) * EP_ + 2 * k]) = make_float2(v.x, v.x);
            *reinterpret_cast<float2*>(&es[(cb + 1) * EP_ + 2 * k]) = make_float2(v.y, v.y);
            *reinterpret_cast<float2*>(&es[(cb + 2) * EP_ + 2 * k]) = make_float2(v.z, v.z);
            *reinterpret_cast<float2*>(&es[(cb + 3) * EP_ + 2 * k]) = make_float2(v.w, v.w);
        }
        __syncthreads();   // es ready

        u64 acc[4][4];
        #pragma unroll
        for (int q = 0; q < 4; ++q)
            #pragma unroll
            for (int i = 0; i < 4; ++i) acc[q][i] = 0ULL;

        #pragma unroll 2
        for (int c = 0; c < CD; ++c) {
            // X: 8 points as 4 natural pairs (broadcast across tc lanes)
            ulonglong2 X0 = *reinterpret_cast<const ulonglong2*>(xr + c * XP_);
            ulonglong2 X1 = *reinterpret_cast<const ulonglong2*>(xr + c * XP_ + 4);
            // E: 4 codes, each duplicated (e,e)
            ulonglong2 E0 = *reinterpret_cast<const ulonglong2*>(er + c * EP_);
            ulonglong2 E1 = *reinterpret_cast<const ulonglong2*>(er + c * EP_ + 4);
            ffma2(acc[0][0], E0.x, X0.x); ffma2(acc[0][1], E0.x, X0.y);
            ffma2(acc[0][2], E0.x, X1.x); ffma2(acc[0][3], E0.x, X1.y);
            ffma2(acc[1][0], E0.y, X0.x); ffma2(acc[1][1], E0.y, X0.y);
            ffma2(acc[1][2], E0.y, X1.x); ffma2(acc[1][3], E0.y, X1.y);
            ffma2(acc[2][0], E1.x, X0.x); ffma2(acc[2][1], E1.x, X0.y);
            ffma2(acc[2][2], E1.x, X1.x); ffma2(acc[2][3], E1.x, X1.y);
            ffma2(acc[3][0], E1.y, X0.x); ffma2(acc[3][1], E1.y, X0.y);
            ffma2(acc[3][2], E1.y, X1.x); ffma2(acc[3][3], E1.y, X1.y);
        }

        // ---- epilogue: d = (a - 2*dot) + esq; k ascending per lane -> strict <
        float4 eq = __ldg(reinterpret_cast<const float4*>(&g_esq[kc * KCH + 4 * tc]));
        #pragma unroll
        for (int q = 0; q < 4; ++q) {
            int k = kc * KCH + 4 * tc + q;
            float esq = (q == 0) ? eq.x : (q == 1) ? eq.y : (q == 2) ? eq.z : eq.w;
            #pragma unroll
            for (int i = 0; i < 4; ++i) {
                float dlo, dhi; unpack2(acc[q][i], dlo, dhi);
                float d0 = __fadd_rn(__fsub_rn(a_[2 * i],     __fmul_rn(2.0f, dlo)), esq);
                float d1 = __fadd_rn(__fsub_rn(a_[2 * i + 1], __fmul_rn(2.0f, dhi)), esq);
                if (d0 < bestv[2 * i])     { bestv[2 * i]     = d0; besti[2 * i]     = k; }
                if (d1 < bestv[2 * i + 1]) { bestv[2 * i + 1] = d1; besti[2 * i + 1] = k; }
            }
        }
    }

    // ---- cross-lane argmin over 16 code lanes
    #pragma unroll
    for (int off = 1; off < 16; off <<= 1) {
        #pragma unroll
        for (int i = 0; i < 8; ++i) {
            float ov = __shfl_xor_sync(0xffffffffu, bestv[i], off);
            int   oi = __shfl_xor_sync(0xffffffffu, besti[i], off);
            if (ov < bestv[i] || (ov == bestv[i] && oi < besti[i])) { bestv[i] = ov; besti[i] = oi; }
        }
    }
    if (tc == 0) {
        #pragma unroll
        for (int i = 0; i < 8; ++i) {
            int p = tr * 8 + i;
            idxs[p] = besti[i];
            out[OFF_IDX + n0 + p] = (float)besti[i];
            atomicAdd(&g_hist[besti[i]], 1u);
        }
    }
    __syncthreads();   // idxs visible; es readers done

    // ---- transpose x into es as [p][TP_] (re-read global, coalesced)
    #pragma unroll
    for (int j = 0; j < 8; ++j) {
        int fid = 8 * t + j;
        int c = fid >> 5;
        int g = fid & 31;
        float4 v = *reinterpret_cast<const float4*>(xbase + (size_t)c * HW + 4 * g);
        es[(4 * g + 0) * TP_ + c] = v.x;
        es[(4 * g + 1) * TP_ + c] = v.y;
        es[(4 * g + 2) * TP_ + c] = v.z;
        es[(4 * g + 3) * TP_ + c] = v.w;
    }
    __syncthreads();

    // ---- quantize + straight-through + loss
    double ls = 0.0;
    #pragma unroll
    for (int i = 0; i < 8; ++i) {
        int p = tr * 8 + i;
        int n = n0 + p;
        int k = idxs[p];
        float4 qv = __ldg(reinterpret_cast<const float4*>(emb + (size_t)k * CD) + tc);
        float4 xv = *reinterpret_cast<const float4*>(&es[p * TP_ + 4 * tc]);
        float e0 = __fsub_rn(qv.x, xv.x);
        float e1 = __fsub_rn(qv.y, xv.y);
        float e2 = __fsub_rn(qv.z, xv.z);
        float e3 = __fsub_rn(qv.w, xv.w);
        float4 o;
        o.x = __fadd_rn(xv.x, e0);
        o.y = __fadd_rn(xv.y, e1);
        o.z = __fadd_rn(xv.z, e2);
        o.w = __fadd_rn(xv.w, e3);
        *reinterpret_cast<float4*>(out + (size_t)n * CD + 4 * tc) = o;
        ls += (double)__fmul_rn(e0, e0) + (double)__fmul_rn(e1, e1)
            + (double)__fmul_rn(e2, e2) + (double)__fmul_rn(e3, e3);
    }
    #pragma unroll
    for (int off = 16; off > 0; off >>= 1)
        ls += __shfl_down_sync(0xffffffffu, ls, off);
    if ((t & 31) == 0) atomicAdd(&g_loss, ls);
}

__global__ void vq_final(float* __restrict__ out) {
    __shared__ double red[256];
    int t = threadIdx.x;
    double s = 0.0;
    for (int k = t; k < KC; k += 256) {
        float cnt = (float)g_hist[k];
        float pr  = __fmul_rn(cnt, 1.0f / 65536.0f);
        float lg  = logf(__fadd_rn(pr, 1e-10f));
        s += (double)__fmul_rn(pr, lg);
    }
    red[t] = s;
    __syncthreads();
    for (int off = 128; off > 0; off >>= 1) {
        if (t < off) red[t] += red[t + off];
        __syncthreads();
    }
    if (t == 0) {
        float m = (float)(g_loss / 4194304.0);
        out[OFF_LOSS] = __fadd_rn(m, __fmul_rn(0.25f, m));
        out[OFF_PERP] = expf(-(float)red[0]);
    }
}

extern "C" void kernel_launch(void* const* d_in, const int* in_sizes, int n_in,
                              void* d_out, int out_size) {
    const float* inputs = (const float*)d_in[0];
    const float* emb    = (const float*)d_in[1];
    if (n_in >= 2 && in_sizes[0] == KC * CD && in_sizes[1] == NPTS * CD) {
        const float* tmp = inputs; inputs = emb; emb = tmp;
    }
    float* out = (float*)d_out;

    cudaFuncSetAttribute(vq_main, cudaFuncAttributeMaxDynamicSharedMemorySize, SMEM_BYTES);

    vq_init<<<1, 1024>>>();
    vq_esq<<<KC / 256, 256>>>(emb);
    vq_main<<<NPTS / MT, 256, SMEM_BYTES>>>(inputs, emb, out);
    vq_final<<<1, 256>>>(out);
}

// round 5
// speedup vs baseline: 1.7225x; 1.7225x over previous
#include <cuda_runtime.h>
#include <math.h>

// VectorQuantizer: N=65536 (64x32x32 BHWC-flat), C=64, K=1024.
// Output (float32): [quantized 4194304][vq_loss 1][indices 65536][perplexity 1]
// Numerics verified bit-exact in R1.

#define NPTS   65536
#define KC     1024
#define CD     64
#define HW     1024
#define MT     128
#define XSTRIDE 132
#define ESTRIDE 68
#define SMEM_FLOATS (CD*XSTRIDE + 128*ESTRIDE + 128)
#define SMEM_BYTES  (SMEM_FLOATS * 4)

#define OFF_LOSS  4194304
#define OFF_IDX   4194305
#define OFF_PERP  4259841

typedef unsigned long long u64;

__device__ float        g_esq[KC];
__device__ int          g_idx[NPTS];
__device__ unsigned int g_hist[KC];
__device__ double       g_loss;

__device__ __forceinline__ u64 pack_dup(float x) {
    u64 r; asm("mov.b64 %0, {%1, %1};" : "=l"(r) : "f"(x)); return r;
}
__device__ __forceinline__ void unpack2(u64 v, float &lo, float &hi) {
    asm("mov.b64 {%0, %1}, %2;" : "=f"(lo), "=f"(hi) : "l"(v));
}
// packed fp32x2 FMA: each lane is IEEE-rn fp32 FMA (bit-identical to scalar FFMA)
__device__ __forceinline__ void ffma2(u64 &acc, u64 a, u64 b) {
    asm("fma.rn.f32x2 %0, %1, %2, %0;" : "+l"(acc) : "l"(a), "l"(b));
}

// ---------------- init ----------------
__global__ void vq_init() {
    int t = blockIdx.x * blockDim.x + threadIdx.x;
    if (t < KC) g_hist[t] = 0u;
    if (t == 0) g_loss = 0.0;
}

// ---------------- esq ----------------
__global__ void vq_esq(const float* __restrict__ emb) {
    int k = blockIdx.x * blockDim.x + threadIdx.x;
    if (k < KC) {
        float s = 0.0f;
        const float* er = emb + (size_t)k * CD;
        #pragma unroll
        for (int c = 0; c < CD; ++c) {
            float e = er[c];
            s = __fadd_rn(s, __fmul_rn(e, e));
        }
        g_esq[k] = s;
    }
}

// ---------------- main: distances + argmin ----------------
__global__ void __launch_bounds__(256) vq_main(const float* __restrict__ inputs,
                                               const float* __restrict__ emb,
                                               float* __restrict__ outIdxF) {
    extern __shared__ float sm[];
    float* xs  = sm;                     // [CD][XSTRIDE]   xs[c*XSTRIDE + p]
    float* es  = sm + CD * XSTRIDE;      // [128][ESTRIDE]  es[kk*ESTRIDE + c]
    float* as_ = es + 128 * ESTRIDE;     // [128]

    const int t  = threadIdx.x;
    const int tr = t >> 4;    // 0..15 point group (8 pts each)
    const int tc = t & 15;    // 0..15 code lane
    const int n0 = blockIdx.x * MT;
    const int b  = n0 >> 10;
    const int p0 = n0 & 1023;
    const float* xbase = inputs + (size_t)b * (CD * HW) + p0;

    // load x tile (transposed into [c][p])
    #pragma unroll
    for (int j = 0; j < 8; ++j) {
        int q  = t + j * 256;
        int c  = q >> 5;
        int i4 = (q & 31) << 2;
        float4 v = *reinterpret_cast<const float4*>(xbase + (size_t)c * HW + i4);
        *reinterpret_cast<float4*>(&xs[c * XSTRIDE + i4]) = v;
    }
    __syncthreads();

    // a = ||x||^2 : strictly sequential fp32
    if (t < MT) {
        float s = 0.0f;
        #pragma unroll
        for (int c = 0; c < CD; ++c) {
            float xv = xs[c * XSTRIDE + t];
            s = __fadd_rn(s, __fmul_rn(xv, xv));
        }
        as_[t] = s;
    }
    __syncthreads();

    // hoist point norms into regs (constant across chunks)
    float a_[8];
    #pragma unroll
    for (int i = 0; i < 8; ++i) a_[i] = as_[tr * 8 + i];

    float bestv[8];
    int   besti[8];
    #pragma unroll
    for (int i = 0; i < 8; ++i) { bestv[i] = __int_as_float(0x7f800000); besti[i] = 0x7fffffff; }

    #pragma unroll 1
    for (int kc = 0; kc < 8; ++kc) {
        __syncthreads();   // es reuse
        // load e chunk: es[kk][c] = emb[(kc*128+kk)*64 + c]
        #pragma unroll
        for (int j = 0; j < 8; ++j) {
            int q  = t + j * 256;
            int kk = q >> 4;
            int cg = (q & 15) << 2;
            float4 v = *reinterpret_cast<const float4*>(emb + (size_t)(kc * 128 + kk) * CD + cg);
            *reinterpret_cast<float4*>(&es[kk * ESTRIDE + cg]) = v;
        }
        __syncthreads();

        u64 acc[8][4];
        #pragma unroll
        for (int j = 0; j < 8; ++j)
            #pragma unroll
            for (int i = 0; i < 4; ++i) acc[j][i] = 0ULL;

        #pragma unroll 4
        for (int c4 = 0; c4 < CD; c4 += 4) {
            float4 ef[8];
            #pragma unroll
            for (int j = 0; j < 8; ++j)
                ef[j] = *reinterpret_cast<const float4*>(&es[(j * 16 + tc) * ESTRIDE + c4]);
            #pragma unroll
            for (int cc = 0; cc < 4; ++cc) {
                // x point-pairs read directly as 64-bit lanes (same LDS.128 as before, no MOV repack)
                const float* xr = &xs[(c4 + cc) * XSTRIDE + tr * 8];
                ulonglong2 Xa = *reinterpret_cast<const ulonglong2*>(xr);
                ulonglong2 Xb = *reinterpret_cast<const ulonglong2*>(xr + 4);
                #pragma unroll
                for (int j = 0; j < 8; ++j) {
                    float ev = (cc == 0) ? ef[j].x : (cc == 1) ? ef[j].y : (cc == 2) ? ef[j].z : ef[j].w;
                    u64 ed = pack_dup(ev);
                    ffma2(acc[j][0], ed, Xa.x);
                    ffma2(acc[j][1], ed, Xa.y);
                    ffma2(acc[j][2], ed, Xb.x);
                    ffma2(acc[j][3], ed, Xb.y);
                }
            }
        }

        // epilogue: d = (a - 2*dot) + esq, argmin (first-index ties)
        #pragma unroll
        for (int j = 0; j < 8; ++j) {
            int k = kc * 128 + j * 16 + tc;
            float esq = __ldg(&g_esq[k]);
            #pragma unroll
            for (int i = 0; i < 4; ++i) {
                float d0, d1; unpack2(acc[j][i], d0, d1);
                int ii = i * 2;
                float dd0 = __fadd_rn(__fsub_rn(a_[ii],     __fmul_rn(2.0f, d0)), esq);
                float dd1 = __fadd_rn(__fsub_rn(a_[ii + 1], __fmul_rn(2.0f, d1)), esq);
                if (dd0 < bestv[ii]     || (dd0 == bestv[ii]     && k < besti[ii]))     { bestv[ii] = dd0;     besti[ii] = k; }
                if (dd1 < bestv[ii + 1] || (dd1 == bestv[ii + 1] && k < besti[ii + 1])) { bestv[ii + 1] = dd1; besti[ii + 1] = k; }
            }
        }
    }

    // cross-lane argmin over the 16 code lanes
    #pragma unroll
    for (int off = 1; off < 16; off <<= 1) {
        #pragma unroll
        for (int i = 0; i < 8; ++i) {
            float ov = __shfl_xor_sync(0xffffffffu, bestv[i], off);
            int   oi = __shfl_xor_sync(0xffffffffu, besti[i], off);
            if (ov < bestv[i] || (ov == bestv[i] && oi < besti[i])) { bestv[i] = ov; besti[i] = oi; }
        }
    }
    if (tc == 0) {
        #pragma unroll
        for (int i = 0; i < 8; ++i) {
            int n = n0 + tr * 8 + i;
            g_idx[n]   = besti[i];
            outIdxF[n] = (float)besti[i];
            atomicAdd(&g_hist[besti[i]], 1u);
        }
    }
}

// ---------------- quantize + loss (coalesced via smem transpose) ----------------
__global__ void __launch_bounds__(256) vq_quant(const float* __restrict__ inputs,
                                                const float* __restrict__ emb,
                                                float* __restrict__ outQ) {
    __shared__ float  xt[CD * 129];
    __shared__ double red[256];

    const int t  = threadIdx.x;
    const int n0 = blockIdx.x * MT;
    const int b  = n0 >> 10;
    const int p0 = n0 & 1023;
    const float* xbase = inputs + (size_t)b * (CD * HW) + p0;

    #pragma unroll
    for (int j = 0; j < 8; ++j) {
        int q = t + j * 256;
        int c = q >> 5;
        int g = q & 31;
        float4 v = *reinterpret_cast<const float4*>(xbase + (size_t)c * HW + 4 * g);
        xt[c * 129 + 4 * g + 0] = v.x;
        xt[c * 129 + 4 * g + 1] = v.y;
        xt[c * 129 + 4 * g + 2] = v.z;
        xt[c * 129 + 4 * g + 3] = v.w;
    }
    __syncthreads();

    const int pc = t & 15;
    const int pg = t >> 4;
    double s = 0.0;

    #pragma unroll
    for (int i = 0; i < 8; ++i) {
        int p = pg * 8 + i;
        int n = n0 + p;
        int ki = g_idx[n];
        float4 qv = __ldg(reinterpret_cast<const float4*>(emb + (size_t)ki * CD + 4 * pc));
        float x0 = xt[(4 * pc + 0) * 129 + p];
        float x1 = xt[(4 * pc + 1) * 129 + p];
        float x2 = xt[(4 * pc + 2) * 129 + p];
        float x3 = xt[(4 * pc + 3) * 129 + p];

        float e0 = __fsub_rn(qv.x, x0);
        float e1 = __fsub_rn(qv.y, x1);
        float e2 = __fsub_rn(qv.z, x2);
        float e3 = __fsub_rn(qv.w, x3);

        float4 o;  // straight-through: x + (q - x)
        o.x = __fadd_rn(x0, e0);
        o.y = __fadd_rn(x1, e1);
        o.z = __fadd_rn(x2, e2);
        o.w = __fadd_rn(x3, e3);
        *reinterpret_cast<float4*>(outQ + (size_t)n * CD + 4 * pc) = o;

        s += (double)__fmul_rn(e0, e0) + (double)__fmul_rn(e1, e1)
           + (double)__fmul_rn(e2, e2) + (double)__fmul_rn(e3, e3);
    }

    red[t] = s;
    __syncthreads();
    for (int off = 128; off > 0; off >>= 1) {
        if (t < off) red[t] += red[t + off];
        __syncthreads();
    }
    if (t == 0) atomicAdd(&g_loss, red[0]);
}

// ---------------- finalize ----------------
__global__ void vq_final(float* __restrict__ out) {
    __shared__ double red[256];
    int t = threadIdx.x;
    double s = 0.0;
    for (int k = t; k < KC; k += 256) {
        float cnt = (float)g_hist[k];
        float pr  = __fmul_rn(cnt, 1.0f / 65536.0f);
        float lg  = logf(__fadd_rn(pr, 1e-10f));
        s += (double)__fmul_rn(pr, lg);
    }
    red[t] = s;
    __syncthreads();
    for (int off = 128; off > 0; off >>= 1) {
        if (t < off) red[t] += red[t + off];
        __syncthreads();
    }
    if (t == 0) {
        float m = (float)(g_loss / 4194304.0);
        out[OFF_LOSS] = __fadd_rn(m, __fmul_rn(0.25f, m));
        out[OFF_PERP] = expf(-(float)red[0]);
    }
}

extern "C" void kernel_launch(void* const* d_in, const int* in_sizes, int n_in,
                              void* d_out, int out_size) {
    const float* inputs = (const float*)d_in[0];
    const float* emb    = (const float*)d_in[1];
    if (n_in >= 2 && in_sizes[0] == KC * CD && in_sizes[1] == NPTS * CD) {
        const float* tmp = inputs; inputs = emb; emb = tmp;
    }
    float* out = (float*)d_out;

    cudaFuncSetAttribute(vq_main, cudaFuncAttributeMaxDynamicSharedMemorySize, SMEM_BYTES);

    vq_init<<<1, 1024>>>();
    vq_esq<<<KC / 256, 256>>>(emb);
    vq_main<<<NPTS / MT, 256, SMEM_BYTES>>>(inputs, emb, out + OFF_IDX);
    vq_quant<<<NPTS / MT, 256>>>(inputs, emb, out);
    vq_final<<<1, 256>>>(out);
}